// round 1
// baseline (speedup 1.0000x reference)
#include <cuda_runtime.h>
#include <cuda_bf16.h>
#include <math.h>

// Problem constants
#define BATCH 4
#define HH 56
#define WW 56
#define CC 256
#define NHEAD 8
#define HD 32
#define KS 7
#define PADR 3
#define M_TOTAL (BATCH * HH * WW)   // 12544
#define QKV_N (3 * CC)              // 768

// Scratch (device globals: allocation-free rule)
__device__ float g_qkv[M_TOTAL * QKV_N];   // [pix][3*256] : q|k|v, q pre-scaled
__device__ float g_attn[M_TOTAL * CC];     // attention output before proj

// ---------------------------------------------------------------------------
// Tiled fp32 GEMM: C[M,N] = A[M,K] @ B[K,N] + bias[N], cols < scaleCols scaled.
// Block tile 128x64, microtile 8x4, BK=16, double-buffered smem.
// Requires M%128==0, N%64==0, K%16==0 (true for all our shapes).
// ---------------------------------------------------------------------------
__global__ __launch_bounds__(256) void sgemm_bias(
    const float* __restrict__ A, const float* __restrict__ B,
    const float* __restrict__ bias, float* __restrict__ C,
    int N, int K, int scaleCols, float scale)
{
    __shared__ float As[2][16][128];   // [buf][k][m] (transposed)
    __shared__ float Bs[2][16][64];    // [buf][k][n]

    const int tid = threadIdx.x;
    const int tx = tid & 15;           // 0..15 -> cols tx*4
    const int ty = tid >> 4;           // 0..15 -> rows ty*8
    const int bm = blockIdx.y << 7;
    const int bn = blockIdx.x << 6;

    // global load mapping
    const int a_row = tid >> 2;        // 0..63
    const int a_kq  = tid & 3;         // 0..3 (k quad)
    const int b_row = tid >> 4;        // 0..15
    const int b_cq  = tid & 15;        // 0..15 (col quad)

    const float* Ap0 = A + (size_t)(bm + a_row) * K + a_kq * 4;
    const float* Ap1 = Ap0 + (size_t)64 * K;
    const float* Bp  = B + (size_t)b_row * N + bn + b_cq * 4;

    float acc[8][4];
    #pragma unroll
    for (int i = 0; i < 8; ++i)
        #pragma unroll
        for (int j = 0; j < 4; ++j) acc[i][j] = 0.f;

    // preload tile 0
    float4 av0 = *(const float4*)Ap0;
    float4 av1 = *(const float4*)Ap1;
    float4 bv  = *(const float4*)Bp;
    As[0][a_kq*4+0][a_row] = av0.x; As[0][a_kq*4+1][a_row] = av0.y;
    As[0][a_kq*4+2][a_row] = av0.z; As[0][a_kq*4+3][a_row] = av0.w;
    As[0][a_kq*4+0][a_row+64] = av1.x; As[0][a_kq*4+1][a_row+64] = av1.y;
    As[0][a_kq*4+2][a_row+64] = av1.z; As[0][a_kq*4+3][a_row+64] = av1.w;
    *(float4*)&Bs[0][b_row][b_cq*4] = bv;
    __syncthreads();

    const int ntiles = K >> 4;
    for (int t = 0; t < ntiles; ++t) {
        const int cur = t & 1;
        if (t + 1 < ntiles) {
            av0 = *(const float4*)(Ap0 + (t + 1) * 16);
            av1 = *(const float4*)(Ap1 + (t + 1) * 16);
            bv  = *(const float4*)(Bp + (size_t)(t + 1) * 16 * N);
        }
        #pragma unroll
        for (int kk = 0; kk < 16; ++kk) {
            float ar[8], br[4];
            *(float4*)&ar[0] = *(const float4*)&As[cur][kk][ty*8];
            *(float4*)&ar[4] = *(const float4*)&As[cur][kk][ty*8 + 4];
            *(float4*)&br[0] = *(const float4*)&Bs[cur][kk][tx*4];
            #pragma unroll
            for (int i = 0; i < 8; ++i)
                #pragma unroll
                for (int j = 0; j < 4; ++j)
                    acc[i][j] = fmaf(ar[i], br[j], acc[i][j]);
        }
        if (t + 1 < ntiles) {
            const int nxt = cur ^ 1;
            As[nxt][a_kq*4+0][a_row] = av0.x; As[nxt][a_kq*4+1][a_row] = av0.y;
            As[nxt][a_kq*4+2][a_row] = av0.z; As[nxt][a_kq*4+3][a_row] = av0.w;
            As[nxt][a_kq*4+0][a_row+64] = av1.x; As[nxt][a_kq*4+1][a_row+64] = av1.y;
            As[nxt][a_kq*4+2][a_row+64] = av1.z; As[nxt][a_kq*4+3][a_row+64] = av1.w;
            *(float4*)&Bs[nxt][b_row][b_cq*4] = bv;
        }
        __syncthreads();
    }

    // epilogue: bias + optional scale
    const float4 bias4 = *(const float4*)&bias[bn + tx*4];
    const float s = (bn < scaleCols) ? scale : 1.f;
    #pragma unroll
    for (int i = 0; i < 8; ++i) {
        const int row = bm + ty*8 + i;
        float4 r;
        r.x = (acc[i][0] + bias4.x) * s;
        r.y = (acc[i][1] + bias4.y) * s;
        r.z = (acc[i][2] + bias4.z) * s;
        r.w = (acc[i][3] + bias4.w) * s;
        *(float4*)&C[(size_t)row * N + bn + tx*4] = r;
    }
}

// ---------------------------------------------------------------------------
// Neighborhood attention. One block = (batch b, head h, 8x8 query tile).
// smem holds the 14x14 zero-padded k/v window for this head (pitch 36 floats)
// plus a 64x53 score buffer. Zero-padded OOB exactly matches reference
// semantics (score = rpb only; v contributes 0; still in softmax denom).
// ---------------------------------------------------------------------------
#define TQ 8
#define WIN 14
#define KP 36            // k/v smem row pitch (floats)
#define SP 53            // score row pitch (floats)
#define ATTN_SMEM_FLOATS (2 * WIN * WIN * KP + 64 * SP)
#define ATTN_SMEM_BYTES (ATTN_SMEM_FLOATS * 4)

__global__ __launch_bounds__(256) void na2d_attn(
    const float* __restrict__ qkv, const float* __restrict__ rpb,
    float* __restrict__ out)
{
    extern __shared__ float sm[];
    float* ks_ = sm;                         // [196][KP]
    float* vs_ = sm + WIN * WIN * KP;        // [196][KP]
    float* sc  = sm + 2 * WIN * WIN * KP;    // [64][SP]

    const int b    = blockIdx.z;
    const int head = blockIdx.y;
    const int tY   = blockIdx.x / 7;
    const int tX   = blockIdx.x - tY * 7;
    const int oy   = tY * TQ;
    const int ox   = tX * TQ;
    const int tid  = threadIdx.x;

    // --- load 14x14 k/v window (zero-padded) ---
    for (int idx = tid; idx < WIN * WIN * 8; idx += 256) {
        const int row = idx >> 3;
        const int d4  = idx & 7;
        const int wy = row / WIN, wx = row - wy * WIN;
        const int gy = oy - PADR + wy, gx = ox - PADR + wx;
        float4 kv = make_float4(0.f, 0.f, 0.f, 0.f);
        float4 vv = make_float4(0.f, 0.f, 0.f, 0.f);
        if (gy >= 0 && gy < HH && gx >= 0 && gx < WW) {
            const float* p = qkv + (size_t)(((b * HH + gy) * WW) + gx) * QKV_N
                           + head * HD + d4 * 4;
            kv = *(const float4*)(p + 256);
            vv = *(const float4*)(p + 512);
        }
        *(float4*)&ks_[row * KP + d4 * 4] = kv;
        *(float4*)&vs_[row * KP + d4 * 4] = vv;
    }

    // --- q into registers (4 threads per query share the same q) ---
    const int qi = tid >> 2;       // 0..63
    const int g  = tid & 3;        // 0..3
    const int qy = qi >> 3, qx = qi & 7;
    const size_t qpix = (size_t)((b * HH + oy + qy) * WW) + ox + qx;
    const float4* qp = (const float4*)(qkv + qpix * QKV_N + head * HD);
    float4 qv[8];
    #pragma unroll
    for (int c = 0; c < 8; ++c) qv[c] = qp[c];

    __syncthreads();

    // --- phase 1: scores (each of the 4 threads handles ~12 neighbors) ---
    #pragma unroll
    for (int jb = 0; jb < 52; jb += 4) {
        const int j = jb + g;
        if (j < 49) {
            const int di = j / 7, dj = j - di * 7;
            const float4* kr = (const float4*)(ks_ + ((qy + di) * WIN + qx + dj) * KP);
            float s = 0.f;
            #pragma unroll
            for (int c = 0; c < 8; ++c) {
                const float4 kk4 = kr[c];
                s = fmaf(qv[c].x, kk4.x, s);
                s = fmaf(qv[c].y, kk4.y, s);
                s = fmaf(qv[c].z, kk4.z, s);
                s = fmaf(qv[c].w, kk4.w, s);
            }
            sc[qi * SP + j] = s + rpb[head * 49 + j];
        }
    }
    __syncthreads();

    // --- phase 2: softmax over 49 (one thread per query; pitch 53 is
    //     conflict-free across 32 lanes) ---
    if (tid < 64) {
        float m = -1e30f;
        #pragma unroll
        for (int j = 0; j < 49; ++j) m = fmaxf(m, sc[tid * SP + j]);
        float ssum = 0.f;
        #pragma unroll
        for (int j = 0; j < 49; ++j) {
            const float e = __expf(sc[tid * SP + j] - m);
            sc[tid * SP + j] = e;
            ssum += e;
        }
        const float inv = 1.f / ssum;
        #pragma unroll
        for (int j = 0; j < 49; ++j) sc[tid * SP + j] *= inv;
    }
    __syncthreads();

    // --- phase 3: AV. thread handles dims [g*8, g*8+8) of its query ---
    float4 a0 = make_float4(0.f, 0.f, 0.f, 0.f);
    float4 a1 = make_float4(0.f, 0.f, 0.f, 0.f);
    int jj = 0;
    #pragma unroll
    for (int di = 0; di < 7; ++di) {
        #pragma unroll
        for (int dj = 0; dj < 7; ++dj) {
            const float w = sc[qi * SP + jj];
            const float4* vr = (const float4*)(vs_ + ((qy + di) * WIN + qx + dj) * KP + g * 8);
            const float4 v0 = vr[0], v1 = vr[1];
            a0.x = fmaf(w, v0.x, a0.x); a0.y = fmaf(w, v0.y, a0.y);
            a0.z = fmaf(w, v0.z, a0.z); a0.w = fmaf(w, v0.w, a0.w);
            a1.x = fmaf(w, v1.x, a1.x); a1.y = fmaf(w, v1.y, a1.y);
            a1.z = fmaf(w, v1.z, a1.z); a1.w = fmaf(w, v1.w, a1.w);
            ++jj;
        }
    }
    float* op = out + qpix * CC + head * HD + g * 8;
    *(float4*)op = a0;
    *(float4*)(op + 4) = a1;
}

// ---------------------------------------------------------------------------
extern "C" void kernel_launch(void* const* d_in, const int* in_sizes, int n_in,
                              void* d_out, int out_size)
{
    (void)in_sizes; (void)n_in; (void)out_size;
    const float* x      = (const float*)d_in[0];
    const float* w_qkv  = (const float*)d_in[1];
    const float* b_qkv  = (const float*)d_in[2];
    const float* rpb    = (const float*)d_in[3];
    const float* w_proj = (const float*)d_in[4];
    const float* b_proj = (const float*)d_in[5];
    float* out = (float*)d_out;

    float* qkvb = nullptr;
    float* attnb = nullptr;
    cudaGetSymbolAddress((void**)&qkvb, g_qkv);
    cudaGetSymbolAddress((void**)&attnb, g_attn);

    cudaFuncSetAttribute(na2d_attn, cudaFuncAttributeMaxDynamicSharedMemorySize,
                         ATTN_SMEM_BYTES);

    const float qscale = 0.17677669529663689f; // 32^-0.5

    // 1) qkv = x @ w_qkv + b_qkv  (q columns pre-scaled)
    sgemm_bias<<<dim3(QKV_N / 64, M_TOTAL / 128), 256>>>(
        x, w_qkv, b_qkv, qkvb, QKV_N, CC, 256, qscale);

    // 2) neighborhood attention
    na2d_attn<<<dim3(49, NHEAD, BATCH), 256, ATTN_SMEM_BYTES>>>(qkvb, rpb, attnb);

    // 3) out = attn @ w_proj + b_proj
    sgemm_bias<<<dim3(CC / 64, M_TOTAL / 128), 256>>>(
        attnb, w_proj, b_proj, out, CC, CC, 0, 1.f);
}

// round 2
// speedup vs baseline: 1.4974x; 1.4974x over previous
#include <cuda_runtime.h>
#include <cuda_bf16.h>
#include <math.h>

// Problem constants
#define BATCH 4
#define HH 56
#define WW 56
#define CC 256
#define NHEAD 8
#define HD 32
#define KS 7
#define PADR 3
#define M_TOTAL (BATCH * HH * WW)   // 12544
#define QKV_N (3 * CC)              // 768

// Scratch (device globals: allocation-free rule)
__device__ float g_qkv[M_TOTAL * QKV_N];   // [pix][3*256] : q|k|v, q pre-scaled
__device__ float g_attn[M_TOTAL * CC];     // attention output before proj

// ---------------------------------------------------------------------------
// TF32 tensor-core GEMM: C[M,N] = A[M,K] @ B[K,N] + bias[N], scaled cols.
// Block tile 128x128x32, 512 threads = 16 warps in 4x4 grid, warp tile 32x32.
// mma.sync.m16n8k8.tf32. Smem stored in 4 (k%4) planes, row pitch 10,
// plane pad 8 -> conflict-free LDS.64 fragment loads.
// Requires M%128==0, N%128==0, K%32==0 (true: 12544, 768/256, 256).
// ---------------------------------------------------------------------------
#define BM 128
#define BN 128
#define BK 32
#define PITCH 10                    // floats per (row) = 8 k4-slots + 2 pad
#define APLANE (BM * PITCH + 8)     // 1288 floats; %32 == 8 (bank-friendly)
#define STAGE_FLOATS (8 * APLANE)   // 4 A planes + 4 B planes
#define GEMM_SMEM_BYTES (2 * STAGE_FLOATS * 4)

__device__ __forceinline__ unsigned f2tf32(float x) {
    unsigned r;
    asm("cvt.rna.tf32.f32 %0, %1;" : "=r"(r) : "f"(x));
    return r;
}

__device__ __forceinline__ void mma_tf32(float4& d,
    unsigned a0, unsigned a1, unsigned a2, unsigned a3,
    unsigned b0, unsigned b1)
{
    asm volatile(
        "mma.sync.aligned.m16n8k8.row.col.f32.tf32.tf32.f32 "
        "{%0,%1,%2,%3},{%4,%5,%6,%7},{%8,%9},{%0,%1,%2,%3};\n"
        : "+f"(d.x), "+f"(d.y), "+f"(d.z), "+f"(d.w)
        : "r"(a0), "r"(a1), "r"(a2), "r"(a3), "r"(b0), "r"(b1));
}

__global__ __launch_bounds__(512) void tgemm_bias(
    const float* __restrict__ A, const float* __restrict__ B,
    const float* __restrict__ bias, float* __restrict__ C,
    int N, int K, int scaleCols, float scale)
{
    extern __shared__ float sm[];
    const int tid  = threadIdx.x;
    const int wid  = tid >> 5;
    const int lane = tid & 31;
    const int warp_m = wid & 3;        // 4 warps along M (32 rows each)
    const int warp_n = wid >> 2;       // 4 warps along N (32 cols each)
    const int c  = lane & 3;           // k%4 plane
    const int qr = lane >> 2;          // quad row 0..7
    const int bm = blockIdx.y << 7;
    const int bn = blockIdx.x << 6 << 1; // blockIdx.x * 128

    // A global: float4 idx i -> m = i>>3, kq = i&7 (K tile has 8 float4/row)
    const int am0 = tid >> 3;          // rows for i0 = tid        (0..63)
    const int am1 = (tid + 512) >> 3;  // rows for i1 = tid + 512  (64..127)
    const int akq = tid & 7;
    const float* Ag0 = A + (size_t)(bm + am0) * K + akq * 4;
    const float* Ag1 = A + (size_t)(bm + am1) * K + akq * 4;

    // B global: scalar elems, flat j = tid + e*512: r = j>>7, n = j&127
    const float* Bg = B + bn + (tid & 127);
    const int br0 = tid >> 7;          // base k-row for e=0 (0..3)

    float acc[2][4][4];
    #pragma unroll
    for (int mt = 0; mt < 2; ++mt)
        #pragma unroll
        for (int nt = 0; nt < 4; ++nt)
            #pragma unroll
            for (int i = 0; i < 4; ++i) acc[mt][nt][i] = 0.f;

    const int ntiles = K >> 5;   // BK=32

    // smem plane bases
    float* As = sm;                    // 4 planes of APLANE
    float* Bs = sm + 4 * APLANE;

    // ---- prologue: stage 0 ----
    {
        float4 a0 = *(const float4*)Ag0;
        float4 a1 = *(const float4*)Ag1;
        float bq[8];
        #pragma unroll
        for (int e = 0; e < 8; ++e)
            bq[e] = Bg[(size_t)(br0 + e * 4) * N];

        float* as = As;
        float* bs = Bs;
        // A: element (m, 4*akq + j) -> plane j, idx m*PITCH + akq
        as[0*APLANE + am0*PITCH + akq] = __uint_as_float(f2tf32(a0.x));
        as[1*APLANE + am0*PITCH + akq] = __uint_as_float(f2tf32(a0.y));
        as[2*APLANE + am0*PITCH + akq] = __uint_as_float(f2tf32(a0.z));
        as[3*APLANE + am0*PITCH + akq] = __uint_as_float(f2tf32(a0.w));
        as[0*APLANE + am1*PITCH + akq] = __uint_as_float(f2tf32(a1.x));
        as[1*APLANE + am1*PITCH + akq] = __uint_as_float(f2tf32(a1.y));
        as[2*APLANE + am1*PITCH + akq] = __uint_as_float(f2tf32(a1.z));
        as[3*APLANE + am1*PITCH + akq] = __uint_as_float(f2tf32(a1.w));
        // B: element (k=r, n) -> plane r&3, idx n*PITCH + (r>>2)
        #pragma unroll
        for (int e = 0; e < 8; ++e) {
            const int r = br0 + e * 4;
            bs[(r & 3)*APLANE + (tid & 127)*PITCH + (r >> 2)] =
                __uint_as_float(f2tf32(bq[e]));
        }
    }
    __syncthreads();

    for (int t = 0; t < ntiles; ++t) {
        // prefetch next tile
        float4 pa0, pa1;
        float pb[8];
        if (t + 1 < ntiles) {
            pa0 = *(const float4*)(Ag0 + (t + 1) * BK);
            pa1 = *(const float4*)(Ag1 + (t + 1) * BK);
            #pragma unroll
            for (int e = 0; e < 8; ++e)
                pb[e] = Bg[(size_t)((t + 1) * BK + br0 + e * 4) * N];
        }

        // compute on stage t&1
        const float* as = sm + (t & 1) * STAGE_FLOATS;
        const float* bs = as + 4 * APLANE;
        #pragma unroll
        for (int s = 0; s < 4; ++s) {
            float2 af[2][2];
            #pragma unroll
            for (int mt = 0; mt < 2; ++mt) {
                const int r0 = warp_m * 32 + mt * 16 + qr;
                af[mt][0] = *(const float2*)(as + c*APLANE + r0*PITCH + 2*s);
                af[mt][1] = *(const float2*)(as + c*APLANE + (r0+8)*PITCH + 2*s);
            }
            float2 bf[4];
            #pragma unroll
            for (int nt = 0; nt < 4; ++nt) {
                const int cn = warp_n * 32 + nt * 8 + qr;
                bf[nt] = *(const float2*)(bs + c*APLANE + cn*PITCH + 2*s);
            }
            #pragma unroll
            for (int mt = 0; mt < 2; ++mt)
                #pragma unroll
                for (int nt = 0; nt < 4; ++nt)
                    mma_tf32(*(float4*)acc[mt][nt],
                             __float_as_uint(af[mt][0].x),
                             __float_as_uint(af[mt][1].x),
                             __float_as_uint(af[mt][0].y),
                             __float_as_uint(af[mt][1].y),
                             __float_as_uint(bf[nt].x),
                             __float_as_uint(bf[nt].y));
        }

        // store next tile into stage (t+1)&1
        if (t + 1 < ntiles) {
            float* nas = sm + ((t + 1) & 1) * STAGE_FLOATS;
            float* nbs = nas + 4 * APLANE;
            nas[0*APLANE + am0*PITCH + akq] = __uint_as_float(f2tf32(pa0.x));
            nas[1*APLANE + am0*PITCH + akq] = __uint_as_float(f2tf32(pa0.y));
            nas[2*APLANE + am0*PITCH + akq] = __uint_as_float(f2tf32(pa0.z));
            nas[3*APLANE + am0*PITCH + akq] = __uint_as_float(f2tf32(pa0.w));
            nas[0*APLANE + am1*PITCH + akq] = __uint_as_float(f2tf32(pa1.x));
            nas[1*APLANE + am1*PITCH + akq] = __uint_as_float(f2tf32(pa1.y));
            nas[2*APLANE + am1*PITCH + akq] = __uint_as_float(f2tf32(pa1.z));
            nas[3*APLANE + am1*PITCH + akq] = __uint_as_float(f2tf32(pa1.w));
            #pragma unroll
            for (int e = 0; e < 8; ++e) {
                const int r = br0 + e * 4;
                nbs[(r & 3)*APLANE + (tid & 127)*PITCH + (r >> 2)] =
                    __uint_as_float(f2tf32(pb[e]));
            }
        }
        __syncthreads();
    }

    // ---- epilogue: bias + optional scale, float2 stores ----
    const float sc = (bn < scaleCols) ? scale : 1.f;
    #pragma unroll
    for (int nt = 0; nt < 4; ++nt) {
        const int gn = bn + warp_n * 32 + nt * 8 + 2 * c;
        const float2 bz = *(const float2*)&bias[gn];
        #pragma unroll
        for (int mt = 0; mt < 2; ++mt) {
            const int gm = bm + warp_m * 32 + mt * 16 + qr;
            float2 r0, r1;
            r0.x = (acc[mt][nt][0] + bz.x) * sc;
            r0.y = (acc[mt][nt][1] + bz.y) * sc;
            r1.x = (acc[mt][nt][2] + bz.x) * sc;
            r1.y = (acc[mt][nt][3] + bz.y) * sc;
            *(float2*)&C[(size_t)gm * N + gn] = r0;
            *(float2*)&C[(size_t)(gm + 8) * N + gn] = r1;
        }
    }
}

// ---------------------------------------------------------------------------
// Neighborhood attention (fp32, unchanged from round 1).
// One block = (batch b, head h, 8x8 query tile).
// ---------------------------------------------------------------------------
#define TQ 8
#define WIN 14
#define KP 36            // k/v smem row pitch (floats)
#define SP 53            // score row pitch (floats)
#define ATTN_SMEM_FLOATS (2 * WIN * WIN * KP + 64 * SP)
#define ATTN_SMEM_BYTES (ATTN_SMEM_FLOATS * 4)

__global__ __launch_bounds__(256) void na2d_attn(
    const float* __restrict__ qkv, const float* __restrict__ rpb,
    float* __restrict__ out)
{
    extern __shared__ float sm[];
    float* ks_ = sm;                         // [196][KP]
    float* vs_ = sm + WIN * WIN * KP;        // [196][KP]
    float* sc  = sm + 2 * WIN * WIN * KP;    // [64][SP]

    const int b    = blockIdx.z;
    const int head = blockIdx.y;
    const int tY   = blockIdx.x / 7;
    const int tX   = blockIdx.x - tY * 7;
    const int oy   = tY * TQ;
    const int ox   = tX * TQ;
    const int tid  = threadIdx.x;

    // --- load 14x14 k/v window (zero-padded) ---
    for (int idx = tid; idx < WIN * WIN * 8; idx += 256) {
        const int row = idx >> 3;
        const int d4  = idx & 7;
        const int wy = row / WIN, wx = row - wy * WIN;
        const int gy = oy - PADR + wy, gx = ox - PADR + wx;
        float4 kv = make_float4(0.f, 0.f, 0.f, 0.f);
        float4 vv = make_float4(0.f, 0.f, 0.f, 0.f);
        if (gy >= 0 && gy < HH && gx >= 0 && gx < WW) {
            const float* p = qkv + (size_t)(((b * HH + gy) * WW) + gx) * QKV_N
                           + head * HD + d4 * 4;
            kv = *(const float4*)(p + 256);
            vv = *(const float4*)(p + 512);
        }
        *(float4*)&ks_[row * KP + d4 * 4] = kv;
        *(float4*)&vs_[row * KP + d4 * 4] = vv;
    }

    // --- q into registers (4 threads per query share the same q) ---
    const int qi = tid >> 2;       // 0..63
    const int g  = tid & 3;        // 0..3
    const int qy = qi >> 3, qx = qi & 7;
    const size_t qpix = (size_t)((b * HH + oy + qy) * WW) + ox + qx;
    const float4* qp = (const float4*)(qkv + qpix * QKV_N + head * HD);
    float4 qv[8];
    #pragma unroll
    for (int c = 0; c < 8; ++c) qv[c] = qp[c];

    __syncthreads();

    // --- phase 1: scores (split accumulators to break FMA chain) ---
    #pragma unroll
    for (int jb = 0; jb < 52; jb += 4) {
        const int j = jb + g;
        if (j < 49) {
            const int di = j / 7, dj = j - di * 7;
            const float4* kr = (const float4*)(ks_ + ((qy + di) * WIN + qx + dj) * KP);
            float s0 = 0.f, s1 = 0.f, s2 = 0.f, s3 = 0.f;
            #pragma unroll
            for (int c = 0; c < 8; c += 2) {
                const float4 k0 = kr[c], k1 = kr[c + 1];
                s0 = fmaf(qv[c].x, k0.x, s0);
                s1 = fmaf(qv[c].y, k0.y, s1);
                s2 = fmaf(qv[c].z, k0.z, s2);
                s3 = fmaf(qv[c].w, k0.w, s3);
                s0 = fmaf(qv[c+1].x, k1.x, s0);
                s1 = fmaf(qv[c+1].y, k1.y, s1);
                s2 = fmaf(qv[c+1].z, k1.z, s2);
                s3 = fmaf(qv[c+1].w, k1.w, s3);
            }
            sc[qi * SP + j] = (s0 + s1) + (s2 + s3) + rpb[head * 49 + j];
        }
    }
    __syncthreads();

    // --- phase 2: softmax over 49 ---
    if (tid < 64) {
        float m = -1e30f;
        #pragma unroll
        for (int j = 0; j < 49; ++j) m = fmaxf(m, sc[tid * SP + j]);
        float ssum = 0.f;
        #pragma unroll
        for (int j = 0; j < 49; ++j) {
            const float e = __expf(sc[tid * SP + j] - m);
            sc[tid * SP + j] = e;
            ssum += e;
        }
        const float inv = 1.f / ssum;
        #pragma unroll
        for (int j = 0; j < 49; ++j) sc[tid * SP + j] *= inv;
    }
    __syncthreads();

    // --- phase 3: AV ---
    float4 a0 = make_float4(0.f, 0.f, 0.f, 0.f);
    float4 a1 = make_float4(0.f, 0.f, 0.f, 0.f);
    int jj = 0;
    #pragma unroll
    for (int di = 0; di < 7; ++di) {
        #pragma unroll
        for (int dj = 0; dj < 7; ++dj) {
            const float w = sc[qi * SP + jj];
            const float4* vr = (const float4*)(vs_ + ((qy + di) * WIN + qx + dj) * KP + g * 8);
            const float4 v0 = vr[0], v1 = vr[1];
            a0.x = fmaf(w, v0.x, a0.x); a0.y = fmaf(w, v0.y, a0.y);
            a0.z = fmaf(w, v0.z, a0.z); a0.w = fmaf(w, v0.w, a0.w);
            a1.x = fmaf(w, v1.x, a1.x); a1.y = fmaf(w, v1.y, a1.y);
            a1.z = fmaf(w, v1.z, a1.z); a1.w = fmaf(w, v1.w, a1.w);
            ++jj;
        }
    }
    float* op = out + qpix * CC + head * HD + g * 8;
    *(float4*)op = a0;
    *(float4*)(op + 4) = a1;
}

// ---------------------------------------------------------------------------
extern "C" void kernel_launch(void* const* d_in, const int* in_sizes, int n_in,
                              void* d_out, int out_size)
{
    (void)in_sizes; (void)n_in; (void)out_size;
    const float* x      = (const float*)d_in[0];
    const float* w_qkv  = (const float*)d_in[1];
    const float* b_qkv  = (const float*)d_in[2];
    const float* rpb    = (const float*)d_in[3];
    const float* w_proj = (const float*)d_in[4];
    const float* b_proj = (const float*)d_in[5];
    float* out = (float*)d_out;

    float* qkvb = nullptr;
    float* attnb = nullptr;
    cudaGetSymbolAddress((void**)&qkvb, g_qkv);
    cudaGetSymbolAddress((void**)&attnb, g_attn);

    cudaFuncSetAttribute(tgemm_bias, cudaFuncAttributeMaxDynamicSharedMemorySize,
                         GEMM_SMEM_BYTES);
    cudaFuncSetAttribute(na2d_attn, cudaFuncAttributeMaxDynamicSharedMemorySize,
                         ATTN_SMEM_BYTES);

    const float qscale = 0.17677669529663689f; // 32^-0.5

    // 1) qkv = x @ w_qkv + b_qkv  (q columns pre-scaled)
    tgemm_bias<<<dim3(QKV_N / 128, M_TOTAL / 128), 512, GEMM_SMEM_BYTES>>>(
        x, w_qkv, b_qkv, qkvb, QKV_N, CC, 256, qscale);

    // 2) neighborhood attention
    na2d_attn<<<dim3(49, NHEAD, BATCH), 256, ATTN_SMEM_BYTES>>>(qkvb, rpb, attnb);

    // 3) out = attn @ w_proj + b_proj
    tgemm_bias<<<dim3(CC / 128, M_TOTAL / 128), 512, GEMM_SMEM_BYTES>>>(
        attnb, w_proj, b_proj, out, CC, CC, 0, 1.f);
}

// round 3
// speedup vs baseline: 1.5697x; 1.0483x over previous
#include <cuda_runtime.h>
#include <cuda_bf16.h>
#include <math.h>

// Problem constants
#define BATCH 4
#define HH 56
#define WW 56
#define CC 256
#define NHEAD 8
#define HD 32
#define KS 7
#define PADR 3
#define M_TOTAL (BATCH * HH * WW)   // 12544
#define QKV_N (3 * CC)              // 768

// Scratch (device globals: allocation-free rule)
__device__ float g_qkv[M_TOTAL * QKV_N];   // [pix][3*256] : q|k|v, q pre-scaled
__device__ float g_attn[M_TOTAL * CC];     // attention output before proj

// ---------------------------------------------------------------------------
// TF32 tensor-core GEMM: C[M,N] = A[M,K] @ B[K,N] + bias[N], scaled cols.
// Block tile 128x64x32, 256 threads = 8 warps in 4(M)x2(N) grid,
// warp tile 32x32. mma.sync.m16n8k8.tf32. Smem in 4 (k%4) planes,
// row pitch 10 -> conflict-free LDS.64 fragment loads.
// 3 blocks/SM (regs capped, smem 62KB).
// ---------------------------------------------------------------------------
#define BM 128
#define BN 64
#define BK 32
#define PITCH 10
#define APLANE (BM * PITCH + 8)       // 1288
#define BPLANE (BN * PITCH + 8)       // 648
#define STAGE_FLOATS (4 * APLANE + 4 * BPLANE)   // 7744
#define GEMM_SMEM_BYTES (2 * STAGE_FLOATS * 4)   // 61952

__device__ __forceinline__ unsigned f2tf32(float x) {
    unsigned r;
    asm("cvt.rna.tf32.f32 %0, %1;" : "=r"(r) : "f"(x));
    return r;
}

__device__ __forceinline__ void mma_tf32(float4& d,
    unsigned a0, unsigned a1, unsigned a2, unsigned a3,
    unsigned b0, unsigned b1)
{
    asm volatile(
        "mma.sync.aligned.m16n8k8.row.col.f32.tf32.tf32.f32 "
        "{%0,%1,%2,%3},{%4,%5,%6,%7},{%8,%9},{%0,%1,%2,%3};\n"
        : "+f"(d.x), "+f"(d.y), "+f"(d.z), "+f"(d.w)
        : "r"(a0), "r"(a1), "r"(a2), "r"(a3), "r"(b0), "r"(b1));
}

__global__ __launch_bounds__(256, 3) void tgemm_bias(
    const float* __restrict__ A, const float* __restrict__ B,
    const float* __restrict__ bias, float* __restrict__ C,
    int N, int K, int scaleCols, float scale)
{
    extern __shared__ float sm[];
    const int tid  = threadIdx.x;
    const int wid  = tid >> 5;
    const int lane = tid & 31;
    const int warp_m = wid & 3;        // 4 warps along M (32 rows each)
    const int warp_n = wid >> 2;       // 2 warps along N (32 cols each)
    const int c  = lane & 3;           // k%4 plane
    const int qr = lane >> 2;          // quad row 0..7
    const int bm = blockIdx.y << 7;
    const int bn = blockIdx.x << 6;

    // A global: 128x32 tile = 1024 float4; thread handles e=0..3, rows +32e
    const int am  = tid >> 3;          // base row 0..31
    const int akq = tid & 7;           // k quad
    const float* Ag = A + (size_t)(bm + am) * K + akq * 4;

    // B global: 32x64 tile = 2048 floats; thread handles e=0..7, k-rows r0+4e
    const int bnn = tid & 63;
    const int br0 = tid >> 6;          // 0..3
    const float* Bg = B + bnn + bn;

    float acc[2][4][4];
    #pragma unroll
    for (int mt = 0; mt < 2; ++mt)
        #pragma unroll
        for (int nt = 0; nt < 4; ++nt)
            #pragma unroll
            for (int i = 0; i < 4; ++i) acc[mt][nt][i] = 0.f;

    const int ntiles = K >> 5;

    // ---- prologue: stage 0 ----
    {
        float4 pa[4];
        float pb[8];
        #pragma unroll
        for (int e = 0; e < 4; ++e)
            pa[e] = *(const float4*)(Ag + (size_t)e * 32 * K);
        #pragma unroll
        for (int e = 0; e < 8; ++e)
            pb[e] = Bg[(size_t)(br0 + e * 4) * N];

        float* as = sm;
        float* bs = sm + 4 * APLANE;
        #pragma unroll
        for (int e = 0; e < 4; ++e) {
            const int m = am + 32 * e;
            as[0*APLANE + m*PITCH + akq] = __uint_as_float(f2tf32(pa[e].x));
            as[1*APLANE + m*PITCH + akq] = __uint_as_float(f2tf32(pa[e].y));
            as[2*APLANE + m*PITCH + akq] = __uint_as_float(f2tf32(pa[e].z));
            as[3*APLANE + m*PITCH + akq] = __uint_as_float(f2tf32(pa[e].w));
        }
        #pragma unroll
        for (int e = 0; e < 8; ++e)
            bs[br0*BPLANE + bnn*PITCH + e] = __uint_as_float(f2tf32(pb[e]));
    }
    __syncthreads();

    for (int t = 0; t < ntiles; ++t) {
        float4 pa[4];
        float pb[8];
        if (t + 1 < ntiles) {
            #pragma unroll
            for (int e = 0; e < 4; ++e)
                pa[e] = *(const float4*)(Ag + (size_t)e * 32 * K + (t + 1) * BK);
            #pragma unroll
            for (int e = 0; e < 8; ++e)
                pb[e] = Bg[(size_t)((t + 1) * BK + br0 + e * 4) * N];
        }

        const float* as = sm + (t & 1) * STAGE_FLOATS;
        const float* bs = as + 4 * APLANE;
        #pragma unroll
        for (int s = 0; s < 4; ++s) {
            float2 af[2][2];
            #pragma unroll
            for (int mt = 0; mt < 2; ++mt) {
                const int r0 = warp_m * 32 + mt * 16 + qr;
                af[mt][0] = *(const float2*)(as + c*APLANE + r0*PITCH + 2*s);
                af[mt][1] = *(const float2*)(as + c*APLANE + (r0+8)*PITCH + 2*s);
            }
            float2 bf[4];
            #pragma unroll
            for (int nt = 0; nt < 4; ++nt) {
                const int cn = warp_n * 32 + nt * 8 + qr;
                bf[nt] = *(const float2*)(bs + c*BPLANE + cn*PITCH + 2*s);
            }
            #pragma unroll
            for (int mt = 0; mt < 2; ++mt)
                #pragma unroll
                for (int nt = 0; nt < 4; ++nt)
                    mma_tf32(*(float4*)acc[mt][nt],
                             __float_as_uint(af[mt][0].x),
                             __float_as_uint(af[mt][1].x),
                             __float_as_uint(af[mt][0].y),
                             __float_as_uint(af[mt][1].y),
                             __float_as_uint(bf[nt].x),
                             __float_as_uint(bf[nt].y));
        }

        if (t + 1 < ntiles) {
            float* nas = sm + ((t + 1) & 1) * STAGE_FLOATS;
            float* nbs = nas + 4 * APLANE;
            #pragma unroll
            for (int e = 0; e < 4; ++e) {
                const int m = am + 32 * e;
                nas[0*APLANE + m*PITCH + akq] = __uint_as_float(f2tf32(pa[e].x));
                nas[1*APLANE + m*PITCH + akq] = __uint_as_float(f2tf32(pa[e].y));
                nas[2*APLANE + m*PITCH + akq] = __uint_as_float(f2tf32(pa[e].z));
                nas[3*APLANE + m*PITCH + akq] = __uint_as_float(f2tf32(pa[e].w));
            }
            #pragma unroll
            for (int e = 0; e < 8; ++e)
                nbs[br0*BPLANE + bnn*PITCH + e] = __uint_as_float(f2tf32(pb[e]));
        }
        __syncthreads();
    }

    // ---- epilogue: bias + optional scale ----
    const float sc = (bn < scaleCols) ? scale : 1.f;
    #pragma unroll
    for (int nt = 0; nt < 4; ++nt) {
        const int gn = bn + warp_n * 32 + nt * 8 + 2 * c;
        const float2 bz = *(const float2*)&bias[gn];
        #pragma unroll
        for (int mt = 0; mt < 2; ++mt) {
            const int gm = bm + warp_m * 32 + mt * 16 + qr;
            float2 r0, r1;
            r0.x = (acc[mt][nt][0] + bz.x) * sc;
            r0.y = (acc[mt][nt][1] + bz.y) * sc;
            r1.x = (acc[mt][nt][2] + bz.x) * sc;
            r1.y = (acc[mt][nt][3] + bz.y) * sc;
            *(float2*)&C[(size_t)gm * N + gn] = r0;
            *(float2*)&C[(size_t)(gm + 8) * N + gn] = r1;
        }
    }
}

// ---------------------------------------------------------------------------
// Neighborhood attention. One block = (batch, head, 8x8 query tile).
// In-register softmax: each thread holds its 12-13 scores; max/sum reduced
// across the 4 lanes of a query quad via shfl; only normalized weights
// are written to smem for the AV phase.
// ---------------------------------------------------------------------------
#define TQ 8
#define WIN 14
#define KP 36            // k/v smem row pitch (floats)
#define SP 53            // score row pitch (floats)
#define ATTN_SMEM_FLOATS (2 * WIN * WIN * KP + 64 * SP + 52)
#define ATTN_SMEM_BYTES (ATTN_SMEM_FLOATS * 4)

__global__ __launch_bounds__(256) void na2d_attn(
    const float* __restrict__ qkv, const float* __restrict__ rpb,
    float* __restrict__ out)
{
    extern __shared__ float sm[];
    float* ks_  = sm;                          // [196][KP]
    float* vs_  = sm + WIN * WIN * KP;         // [196][KP]
    float* sc   = sm + 2 * WIN * WIN * KP;     // [64][SP]
    float* rpbs = sc + 64 * SP;                // [49]

    const int b    = blockIdx.z;
    const int head = blockIdx.y;
    const int tY   = blockIdx.x / 7;
    const int tX   = blockIdx.x - tY * 7;
    const int oy   = tY * TQ;
    const int ox   = tX * TQ;
    const int tid  = threadIdx.x;

    // --- load 14x14 k/v window (zero-padded) + rpb row ---
    if (tid < 49) rpbs[tid] = rpb[head * 49 + tid];
    for (int idx = tid; idx < WIN * WIN * 8; idx += 256) {
        const int row = idx >> 3;
        const int d4  = idx & 7;
        const int wy = row / WIN, wx = row - wy * WIN;
        const int gy = oy - PADR + wy, gx = ox - PADR + wx;
        float4 kv = make_float4(0.f, 0.f, 0.f, 0.f);
        float4 vv = make_float4(0.f, 0.f, 0.f, 0.f);
        if (gy >= 0 && gy < HH && gx >= 0 && gx < WW) {
            const float* p = qkv + (size_t)(((b * HH + gy) * WW) + gx) * QKV_N
                           + head * HD + d4 * 4;
            kv = *(const float4*)(p + 256);
            vv = *(const float4*)(p + 512);
        }
        *(float4*)&ks_[row * KP + d4 * 4] = kv;
        *(float4*)&vs_[row * KP + d4 * 4] = vv;
    }

    // --- q into registers (4 threads per query share the same q) ---
    const int qi = tid >> 2;       // 0..63
    const int g  = tid & 3;        // 0..3
    const int qy = qi >> 3, qx = qi & 7;
    const size_t qpix = (size_t)((b * HH + oy + qy) * WW) + ox + qx;
    const float4* qp = (const float4*)(qkv + qpix * QKV_N + head * HD);
    float4 qv[8];
    #pragma unroll
    for (int cc = 0; cc < 8; ++cc) qv[cc] = qp[cc];

    __syncthreads();

    // --- phase 1: scores in registers ---
    float sv[13];
    #pragma unroll
    for (int u = 0; u < 13; ++u) {
        const int j = g + 4 * u;
        const bool act = (j < 49);
        const int jc = act ? j : 48;
        const int di = jc / 7, dj = jc - di * 7;
        const float4* kr = (const float4*)(ks_ + ((qy + di) * WIN + qx + dj) * KP);
        float s0 = 0.f, s1 = 0.f, s2 = 0.f, s3 = 0.f;
        #pragma unroll
        for (int cc = 0; cc < 8; cc += 2) {
            const float4 k0 = kr[cc], k1 = kr[cc + 1];
            s0 = fmaf(qv[cc].x, k0.x, s0);
            s1 = fmaf(qv[cc].y, k0.y, s1);
            s2 = fmaf(qv[cc].z, k0.z, s2);
            s3 = fmaf(qv[cc].w, k0.w, s3);
            s0 = fmaf(qv[cc+1].x, k1.x, s0);
            s1 = fmaf(qv[cc+1].y, k1.y, s1);
            s2 = fmaf(qv[cc+1].z, k1.z, s2);
            s3 = fmaf(qv[cc+1].w, k1.w, s3);
        }
        sv[u] = act ? ((s0 + s1) + (s2 + s3) + rpbs[jc]) : -1e30f;
    }

    // --- softmax across quad (lanes of a query are adjacent) ---
    float m = sv[0];
    #pragma unroll
    for (int u = 1; u < 13; ++u) m = fmaxf(m, sv[u]);
    m = fmaxf(m, __shfl_xor_sync(0xffffffffu, m, 1));
    m = fmaxf(m, __shfl_xor_sync(0xffffffffu, m, 2));
    float ssum = 0.f;
    #pragma unroll
    for (int u = 0; u < 13; ++u) {
        const float e = __expf(sv[u] - m);
        sv[u] = e;
        ssum += e;
    }
    ssum += __shfl_xor_sync(0xffffffffu, ssum, 1);
    ssum += __shfl_xor_sync(0xffffffffu, ssum, 2);
    const float inv = 1.f / ssum;
    #pragma unroll
    for (int u = 0; u < 13; ++u) {
        const int j = g + 4 * u;
        if (j < 49) sc[qi * SP + j] = sv[u] * inv;
    }
    __syncthreads();

    // --- phase 3: AV. thread handles dims [g*8, g*8+8) of its query ---
    float4 a0 = make_float4(0.f, 0.f, 0.f, 0.f);
    float4 a1 = make_float4(0.f, 0.f, 0.f, 0.f);
    int jj = 0;
    #pragma unroll
    for (int di = 0; di < 7; ++di) {
        #pragma unroll
        for (int dj = 0; dj < 7; ++dj) {
            const float w = sc[qi * SP + jj];
            const float4* vr = (const float4*)(vs_ + ((qy + di) * WIN + qx + dj) * KP + g * 8);
            const float4 v0 = vr[0], v1 = vr[1];
            a0.x = fmaf(w, v0.x, a0.x); a0.y = fmaf(w, v0.y, a0.y);
            a0.z = fmaf(w, v0.z, a0.z); a0.w = fmaf(w, v0.w, a0.w);
            a1.x = fmaf(w, v1.x, a1.x); a1.y = fmaf(w, v1.y, a1.y);
            a1.z = fmaf(w, v1.z, a1.z); a1.w = fmaf(w, v1.w, a1.w);
            ++jj;
        }
    }
    float* op = out + qpix * CC + head * HD + g * 8;
    *(float4*)op = a0;
    *(float4*)(op + 4) = a1;
}

// ---------------------------------------------------------------------------
extern "C" void kernel_launch(void* const* d_in, const int* in_sizes, int n_in,
                              void* d_out, int out_size)
{
    (void)in_sizes; (void)n_in; (void)out_size;
    const float* x      = (const float*)d_in[0];
    const float* w_qkv  = (const float*)d_in[1];
    const float* b_qkv  = (const float*)d_in[2];
    const float* rpb    = (const float*)d_in[3];
    const float* w_proj = (const float*)d_in[4];
    const float* b_proj = (const float*)d_in[5];
    float* out = (float*)d_out;

    float* qkvb = nullptr;
    float* attnb = nullptr;
    cudaGetSymbolAddress((void**)&qkvb, g_qkv);
    cudaGetSymbolAddress((void**)&attnb, g_attn);

    cudaFuncSetAttribute(tgemm_bias, cudaFuncAttributeMaxDynamicSharedMemorySize,
                         GEMM_SMEM_BYTES);
    cudaFuncSetAttribute(na2d_attn, cudaFuncAttributeMaxDynamicSharedMemorySize,
                         ATTN_SMEM_BYTES);

    const float qscale = 0.17677669529663689f; // 32^-0.5

    // 1) qkv = x @ w_qkv + b_qkv  (q columns pre-scaled)
    tgemm_bias<<<dim3(QKV_N / 64, M_TOTAL / 128), 256, GEMM_SMEM_BYTES>>>(
        x, w_qkv, b_qkv, qkvb, QKV_N, CC, 256, qscale);

    // 2) neighborhood attention
    na2d_attn<<<dim3(49, NHEAD, BATCH), 256, ATTN_SMEM_BYTES>>>(qkvb, rpb, attnb);

    // 3) out = attn @ w_proj + b_proj
    tgemm_bias<<<dim3(CC / 64, M_TOTAL / 128), 256, GEMM_SMEM_BYTES>>>(
        attnb, w_proj, b_proj, out, CC, CC, 0, 1.f);
}